// round 9
// baseline (speedup 1.0000x reference)
#include <cuda_runtime.h>
#include <cuda_bf16.h>
#include <cstdint>

#define HIDDEN     128
#define OUT_EMB    256
#define NUM_LAYERS 3
#define NUM_EDGES  1000000
#define NUM_NODES  50000

// ---------------- scratch ----------------------------------------------------
__device__ float g_v[(size_t)NUM_NODES * HIDDEN];
__device__ int   g_idx_is64;
// pre-split weights: layer0 [256][128], layers1-3 [256][256]; hi + lo bf16
#define WTOT (256*128 + 3*256*256)   // 229376
__device__ __align__(16) __nv_bfloat16 g_wh[WTOT];
__device__ __align__(16) __nv_bfloat16 g_wl[WTOT];

// ---------------- small helpers ---------------------------------------------
__device__ __forceinline__ uint32_t smem_u32(const void* p) {
    uint32_t a;
    asm("{ .reg .u64 t; cvta.to.shared.u64 t, %1; cvt.u32.u64 %0, t; }"
        : "=r"(a) : "l"(p));
    return a;
}
__device__ __forceinline__ void bsplit(float x, float& h, float& l) {
    __nv_bfloat16 b = __float2bfloat16(x);
    h = __bfloat162float(b);
    l = x - h;
}
__device__ __forceinline__ uint32_t packbf2(float lo, float hi) {
    __nv_bfloat162 v = __halves2bfloat162(__float2bfloat16(lo), __float2bfloat16(hi));
    return *reinterpret_cast<uint32_t*>(&v);
}
__device__ __forceinline__ void ldsm4(uint32_t* r, uint32_t addr) {
    asm volatile("ldmatrix.sync.aligned.m8n8.x4.shared.b16 {%0,%1,%2,%3}, [%4];"
                 : "=r"(r[0]), "=r"(r[1]), "=r"(r[2]), "=r"(r[3]) : "r"(addr));
}
__device__ __forceinline__ void mma16816(float* d, const uint32_t* a, const uint32_t* b) {
    asm volatile("mma.sync.aligned.m16n8k16.row.col.f32.bf16.bf16.f32 "
                 "{%0,%1,%2,%3}, {%4,%5,%6,%7}, {%8,%9}, {%0,%1,%2,%3};"
                 : "+f"(d[0]), "+f"(d[1]), "+f"(d[2]), "+f"(d[3])
                 : "r"(a[0]), "r"(a[1]), "r"(a[2]), "r"(a[3]),
                   "r"(b[0]), "r"(b[1]));
}
__device__ __forceinline__ float silu(float x) { return x / (1.f + __expf(-x)); }

// ---------------- front kernels ----------------------------------------------
__global__ void detect_idx_kernel(const int* __restrict__ idx) {
    if (blockIdx.x == 0 && threadIdx.x == 0) {
        int z = 0;
        #pragma unroll
        for (int j = 1; j < 64; j += 2) z |= idx[j];
        g_idx_is64 = (z == 0) ? 1 : 0;
    }
}

__global__ void zero_v_kernel() {
    const int i  = blockIdx.x * blockDim.x + threadIdx.x;
    const int n4 = NUM_NODES * HIDDEN / 4;
    if (i < n4) reinterpret_cast<float4*>(g_v)[i] = make_float4(0.f, 0.f, 0.f, 0.f);
}

__global__ void presplit_kernel(const float* __restrict__ W_up,
                                const float* __restrict__ Ws) {
    const int i = blockIdx.x * blockDim.x + threadIdx.x;
    if (i >= WTOT) return;
    const float v = (i < 256 * 128) ? W_up[i] : Ws[i - 256 * 128];
    float h, l;
    bsplit(v, h, l);
    g_wh[i] = __float2bfloat16(h);
    g_wl[i] = __float2bfloat16(l);
}

__global__ void scatter_kernel(const float4* __restrict__ e2,
                               const void*   __restrict__ idx_raw) {
    const long long g = (long long)blockIdx.x * blockDim.x + threadIdx.x;
    if (g >= (long long)NUM_EDGES * 32) return;
    const int edge = (int)(g >> 5);
    const int lane = (int)(g & 31);
    int node;
    if (g_idx_is64) node = (int)reinterpret_cast<const long long*>(idx_raw)[edge];
    else            node = reinterpret_cast<const int*>(idx_raw)[edge];
    const float4 val = e2[(long long)edge * 32 + lane];
    float* dst = g_v + (size_t)node * HIDDEN + (size_t)lane * 4;
    asm volatile("red.global.add.v4.f32 [%0], {%1, %2, %3, %4};"
                 :: "l"(dst), "f"(val.x), "f"(val.y), "f"(val.z), "f"(val.w)
                 : "memory");
}

// ---------------- tensor-core MLP --------------------------------------------
// SMEM layout (bytes). A rows: 528 B (264 bf16). B rows: 80 B (32 bf16 + pad),
// 16B-aligned, 20-bank step -> conflict-free ldsm/STS phases.
#define SM_A_HI  0
#define SM_A_LO  33792                      // 64*528
#define BROW     80
#define BMAT     20480                      // 256*80 (one hi or lo matrix)
#define BSLOT    40960                      // hi + lo
#define SM_B     67584
#define SM_BIAS  149504                     // 67584 + 2*40960
#define SM_WOUT  150528
#define SM_PART  151552
#define SMEM_BYTES 152576

__global__ void __launch_bounds__(256, 1)
mlp_mma_kernel(const float* __restrict__ b_up, const float* __restrict__ bs,
               const float* __restrict__ W_out, float* __restrict__ out)
{
    extern __shared__ char smem[];
    const uint32_t sb = smem_u32(smem);
    const int t   = threadIdx.x;
    const int wid = t >> 5;
    const int lid = t & 31;
    const int wm  = wid >> 2;      // 0..1 : rows wm*32..+31
    const int wn  = wid & 3;       // 0..3 : cols wn*64..+63
    const int node0 = blockIdx.x * 64;

    // ---- initial A: g_v rows -> bf16 hi/lo split into SMEM ----
    {
        const int m   = t >> 2;
        const int kc0 = (t & 3) * 32;
        const int node = node0 + m;
        float x[32];
        if (node < NUM_NODES) {
            const float4* src =
                reinterpret_cast<const float4*>(g_v + (size_t)node * HIDDEN + kc0);
            #pragma unroll
            for (int i = 0; i < 8; ++i) {
                const float4 v4 = src[i];
                x[4*i] = v4.x; x[4*i+1] = v4.y; x[4*i+2] = v4.z; x[4*i+3] = v4.w;
            }
        } else {
            #pragma unroll
            for (int i = 0; i < 32; ++i) x[i] = 0.f;
        }
        uint32_t hi[16], lo[16];
        #pragma unroll
        for (int j = 0; j < 16; ++j) {
            float h0, l0, h1, l1;
            bsplit(x[2*j], h0, l0);
            bsplit(x[2*j+1], h1, l1);
            hi[j] = packbf2(h0, h1);
            lo[j] = packbf2(l0, l1);
        }
        char* dh = smem + SM_A_HI + m * 528 + kc0 * 2;
        char* dl = smem + SM_A_LO + m * 528 + kc0 * 2;
        #pragma unroll
        for (int u = 0; u < 4; ++u) {
            *reinterpret_cast<uint4*>(dh + u * 16) =
                make_uint4(hi[4*u], hi[4*u+1], hi[4*u+2], hi[4*u+3]);
            *reinterpret_cast<uint4*>(dl + u * 16) =
                make_uint4(lo[4*u], lo[4*u+1], lo[4*u+2], lo[4*u+3]);
        }
    }

    float acc[2][8][4];

    for (int layer = 0; layer < 4; ++layer) {
        const int K    = (layer == 0) ? HIDDEN : OUT_EMB;
        const int npan = K / 32;
        const int Loff = (layer == 0) ? 0 : 256 * 128 + (layer - 1) * 256 * 256;

        // ---- per-layer constants + stage panel 0 (32 k-deep, full rows) ----
        {
            reinterpret_cast<float*>(smem + SM_BIAS)[t] =
                (layer == 0) ? b_up[t] : bs[(layer - 1) * OUT_EMB + t];
            if (layer == 3)
                reinterpret_cast<float*>(smem + SM_WOUT)[t] = W_out[t];
            const int n = t;                 // one row per thread
            char* dH = smem + SM_B + n * BROW;
            char* dL = dH + BMAT;
            #pragma unroll
            for (int c = 0; c < 4; ++c) {    // 4 x uint4 = 32 bf16 (full panel row)
                const int src = Loff + n * K + c * 8;
                *reinterpret_cast<uint4*>(dH + c * 16) =
                    *reinterpret_cast<const uint4*>(g_wh + src);
                *reinterpret_cast<uint4*>(dL + c * 16) =
                    *reinterpret_cast<const uint4*>(g_wl + src);
            }
        }
        __syncthreads();

        #pragma unroll
        for (int ma = 0; ma < 2; ++ma)
            #pragma unroll
            for (int na = 0; na < 8; ++na)
                #pragma unroll
                for (int i = 0; i < 4; ++i) acc[ma][na][i] = 0.f;

        for (int p = 0; p < npan; ++p) {
            const bool hasNext = (p + 1 < npan);
            uint4 pfH[4], pfL[4];
            if (hasNext) {
                const int src0 = Loff + t * K + (p + 1) * 32;
                #pragma unroll
                for (int c = 0; c < 4; ++c) {
                    pfH[c] = *reinterpret_cast<const uint4*>(g_wh + src0 + c * 8);
                    pfL[c] = *reinterpret_cast<const uint4*>(g_wl + src0 + c * 8);
                }
            }

            // ---- compute panel p (k = p*32 .. +31) ----
            const uint32_t bsH = sb + SM_B + (uint32_t)(p & 1) * BSLOT;
            #pragma unroll
            for (int ks = 0; ks < 2; ++ks) {
                const int kk = ks * 16;
                uint32_t Ah[2][4], Al[2][4];
                #pragma unroll
                for (int ma = 0; ma < 2; ++ma) {
                    const int row = wm * 32 + ma * 16 + (lid & 7) + ((lid >> 3) & 1) * 8;
                    const int kc  = p * 32 + kk + (lid >> 4) * 8;
                    const uint32_t ad = sb + SM_A_HI + row * 528 + kc * 2;
                    ldsm4(Ah[ma], ad);
                    ldsm4(Al[ma], ad + 33792);
                }
                uint32_t Bh[8][2], Bl[8][2];
                #pragma unroll
                for (int bp = 0; bp < 4; ++bp) {
                    const int n  = wn * 64 + bp * 16 + (lid & 7) + (lid >> 4) * 8;
                    const int kb = kk + ((lid >> 3) & 1) * 8;
                    const uint32_t ad = bsH + n * BROW + kb * 2;
                    uint32_t r[4];
                    ldsm4(r, ad);
                    Bh[2*bp][0] = r[0]; Bh[2*bp][1] = r[1];
                    Bh[2*bp+1][0] = r[2]; Bh[2*bp+1][1] = r[3];
                    ldsm4(r, ad + BMAT);
                    Bl[2*bp][0] = r[0]; Bl[2*bp][1] = r[1];
                    Bl[2*bp+1][0] = r[2]; Bl[2*bp+1][1] = r[3];
                }
                #pragma unroll
                for (int ma = 0; ma < 2; ++ma)
                    #pragma unroll
                    for (int na = 0; na < 8; ++na) {
                        mma16816(acc[ma][na], Ah[ma], Bh[na]);
                        mma16816(acc[ma][na], Ah[ma], Bl[na]);
                        mma16816(acc[ma][na], Al[ma], Bh[na]);
                    }
            }

            if (hasNext) {
                char* dH = smem + SM_B + ((p + 1) & 1) * BSLOT + t * BROW;
                char* dL = dH + BMAT;
                #pragma unroll
                for (int c = 0; c < 4; ++c) {
                    *reinterpret_cast<uint4*>(dH + c * 16) = pfH[c];
                    *reinterpret_cast<uint4*>(dL + c * 16) = pfL[c];
                }
            }
            __syncthreads();
        }

        // ---- epilogue ----
        const float* bias_s = reinterpret_cast<const float*>(smem + SM_BIAS);
        if (layer < 3) {
            #pragma unroll
            for (int ma = 0; ma < 2; ++ma)
                #pragma unroll
                for (int na = 0; na < 8; ++na) {
                    const int col = wn * 64 + na * 8 + (lid & 3) * 2;
                    const int r0  = wm * 32 + ma * 16 + (lid >> 2);
                    const float bv0 = bias_s[col], bv1 = bias_s[col + 1];
                    float x0 = acc[ma][na][0] + bv0;
                    float x1 = acc[ma][na][1] + bv1;
                    float x2 = acc[ma][na][2] + bv0;
                    float x3 = acc[ma][na][3] + bv1;
                    if (layer > 0) { x0 = silu(x0); x1 = silu(x1); x2 = silu(x2); x3 = silu(x3); }
                    float h0,l0,h1,l1,h2,l2,h3,l3;
                    bsplit(x0,h0,l0); bsplit(x1,h1,l1);
                    bsplit(x2,h2,l2); bsplit(x3,h3,l3);
                    *reinterpret_cast<uint32_t*>(smem + SM_A_HI + r0*528 + col*2) = packbf2(h0,h1);
                    *reinterpret_cast<uint32_t*>(smem + SM_A_LO + r0*528 + col*2) = packbf2(l0,l1);
                    *reinterpret_cast<uint32_t*>(smem + SM_A_HI + (r0+8)*528 + col*2) = packbf2(h2,h3);
                    *reinterpret_cast<uint32_t*>(smem + SM_A_LO + (r0+8)*528 + col*2) = packbf2(l2,l3);
                }
            __syncthreads();
        } else {
            const float* wo = reinterpret_cast<const float*>(smem + SM_WOUT);
            float* part = reinterpret_cast<float*>(smem + SM_PART);
            #pragma unroll
            for (int ma = 0; ma < 2; ++ma) {
                float p0 = 0.f, p1 = 0.f;
                #pragma unroll
                for (int na = 0; na < 8; ++na) {
                    const int col = wn * 64 + na * 8 + (lid & 3) * 2;
                    const float bv0 = bias_s[col], bv1 = bias_s[col + 1];
                    const float w0 = wo[col], w1 = wo[col + 1];
                    p0 = fmaf(silu(acc[ma][na][0] + bv0), w0, p0);
                    p0 = fmaf(silu(acc[ma][na][1] + bv1), w1, p0);
                    p1 = fmaf(silu(acc[ma][na][2] + bv0), w0, p1);
                    p1 = fmaf(silu(acc[ma][na][3] + bv1), w1, p1);
                }
                p0 += __shfl_xor_sync(0xffffffffu, p0, 1);
                p0 += __shfl_xor_sync(0xffffffffu, p0, 2);
                p1 += __shfl_xor_sync(0xffffffffu, p1, 1);
                p1 += __shfl_xor_sync(0xffffffffu, p1, 2);
                if ((lid & 3) == 0) {
                    const int r0 = wm * 32 + ma * 16 + (lid >> 2);
                    part[r0 * 4 + wn]       = p0;
                    part[(r0 + 8) * 4 + wn] = p1;
                }
            }
            __syncthreads();
            if (t < 64) {
                const int node = node0 + t;
                if (node < NUM_NODES)
                    out[node] = part[4*t] + part[4*t+1] + part[4*t+2] + part[4*t+3];
            }
        }
    }
}

// ---------------------------------------------------------------------------
extern "C" void kernel_launch(void* const* d_in, const int* in_sizes, int n_in,
                              void* d_out, int out_size)
{
    const float* e2    = (const float*)d_in[0];
    const void*  idx   = d_in[1];
    const float* W_up  = (const float*)d_in[2];
    const float* b_up  = (const float*)d_in[3];
    const float* Ws    = (const float*)d_in[4];
    const float* bs    = (const float*)d_in[5];
    const float* W_out = (const float*)d_in[6];
    float* out = (float*)d_out;

    cudaFuncSetAttribute(mlp_mma_kernel,
                         cudaFuncAttributeMaxDynamicSharedMemorySize, SMEM_BYTES);

    detect_idx_kernel<<<1, 1>>>((const int*)idx);
    presplit_kernel<<<(WTOT + 255) / 256, 256>>>(W_up, Ws);

    const int n4 = NUM_NODES * HIDDEN / 4;
    zero_v_kernel<<<(n4 + 255) / 256, 256>>>();

    const long long scatter_threads = (long long)NUM_EDGES * 32;
    scatter_kernel<<<(int)((scatter_threads + 255) / 256), 256>>>(
        (const float4*)e2, idx);

    const int mlp_blocks = (NUM_NODES + 63) / 64;   // 782
    mlp_mma_kernel<<<mlp_blocks, 256, SMEM_BYTES>>>(b_up, bs, W_out, out);
}

// round 12
// speedup vs baseline: 1.8432x; 1.8432x over previous
#include <cuda_runtime.h>
#include <cuda_bf16.h>
#include <cstdint>

#define HIDDEN     128
#define OUT_EMB    256
#define NUM_LAYERS 3
#define NUM_EDGES  1000000
#define NUM_NODES  50000

// ---------------- scratch ----------------------------------------------------
__device__ float g_v[(size_t)NUM_NODES * HIDDEN];
__device__ int   g_idx_is64;
// pre-split weights: layer0 [256][128], layers1-3 [256][256]; hi + lo bf16
#define WTOT (256*128 + 3*256*256)   // 229376
__device__ __align__(16) __nv_bfloat16 g_wh[WTOT];
__device__ __align__(16) __nv_bfloat16 g_wl[WTOT];

// ---------------- small helpers ---------------------------------------------
__device__ __forceinline__ uint32_t smem_u32(const void* p) {
    uint32_t a;
    asm("{ .reg .u64 t; cvta.to.shared.u64 t, %1; cvt.u32.u64 %0, t; }"
        : "=r"(a) : "l"(p));
    return a;
}
__device__ __forceinline__ void bsplit(float x, float& h, float& l) {
    __nv_bfloat16 b = __float2bfloat16(x);
    h = __bfloat162float(b);
    l = x - h;
}
__device__ __forceinline__ uint32_t packbf2(float lo, float hi) {
    __nv_bfloat162 v = __halves2bfloat162(__float2bfloat16(lo), __float2bfloat16(hi));
    return *reinterpret_cast<uint32_t*>(&v);
}
__device__ __forceinline__ void ldsm4(uint32_t* r, uint32_t addr) {
    asm volatile("ldmatrix.sync.aligned.m8n8.x4.shared.b16 {%0,%1,%2,%3}, [%4];"
                 : "=r"(r[0]), "=r"(r[1]), "=r"(r[2]), "=r"(r[3]) : "r"(addr));
}
__device__ __forceinline__ void mma16816(float* d, const uint32_t* a, const uint32_t* b) {
    asm volatile("mma.sync.aligned.m16n8k16.row.col.f32.bf16.bf16.f32 "
                 "{%0,%1,%2,%3}, {%4,%5,%6,%7}, {%8,%9}, {%0,%1,%2,%3};"
                 : "+f"(d[0]), "+f"(d[1]), "+f"(d[2]), "+f"(d[3])
                 : "r"(a[0]), "r"(a[1]), "r"(a[2]), "r"(a[3]),
                   "r"(b[0]), "r"(b[1]));
}
__device__ __forceinline__ float silu(float x) { return x / (1.f + __expf(-x)); }

// ---------------- front kernels ----------------------------------------------
__global__ void detect_idx_kernel(const int* __restrict__ idx) {
    if (blockIdx.x == 0 && threadIdx.x == 0) {
        int z = 0;
        #pragma unroll
        for (int j = 1; j < 64; j += 2) z |= idx[j];
        g_idx_is64 = (z == 0) ? 1 : 0;
    }
}

__global__ void zero_v_kernel() {
    const int i  = blockIdx.x * blockDim.x + threadIdx.x;
    const int n4 = NUM_NODES * HIDDEN / 4;
    if (i < n4) reinterpret_cast<float4*>(g_v)[i] = make_float4(0.f, 0.f, 0.f, 0.f);
}

__global__ void presplit_kernel(const float* __restrict__ W_up,
                                const float* __restrict__ Ws) {
    const int i = blockIdx.x * blockDim.x + threadIdx.x;
    if (i >= WTOT) return;
    const float v = (i < 256 * 128) ? W_up[i] : Ws[i - 256 * 128];
    float h, l;
    bsplit(v, h, l);
    g_wh[i] = __float2bfloat16(h);
    g_wl[i] = __float2bfloat16(l);
}

__global__ void scatter_kernel(const float4* __restrict__ e2,
                               const void*   __restrict__ idx_raw) {
    const long long g = (long long)blockIdx.x * blockDim.x + threadIdx.x;
    if (g >= (long long)NUM_EDGES * 32) return;
    const int edge = (int)(g >> 5);
    const int lane = (int)(g & 31);
    int node;
    if (g_idx_is64) node = (int)reinterpret_cast<const long long*>(idx_raw)[edge];
    else            node = reinterpret_cast<const int*>(idx_raw)[edge];
    const float4 val = e2[(long long)edge * 32 + lane];
    float* dst = g_v + (size_t)node * HIDDEN + (size_t)lane * 4;
    asm volatile("red.global.add.v4.f32 [%0], {%1, %2, %3, %4};"
                 :: "l"(dst), "f"(val.x), "f"(val.y), "f"(val.z), "f"(val.w)
                 : "memory");
}

// ---------------- tensor-core MLP (512 threads, 16 warps) ---------------------
// Warp w: wm = w&3 -> rows wm*16..+15 ; wn = w>>2 -> cols wn*64..+63.
// Per warp per k16-step: 2 A-ldsm (hi/lo) + 8 B-ldsm, 24 HMMA (8 tiles x 3).
// SMEM: A rows 528 B; B rows 80 B (conflict-free phases), double-buffered.
#define SM_A_HI  0
#define SM_A_LO  33792                      // 64*528
#define BROW     80
#define BMAT     20480                      // 256*80
#define BSLOT    40960                      // hi + lo
#define SM_B     67584
#define SM_BIAS  149504
#define SM_WOUT  150528
#define SM_PART  151552
#define SMEM_BYTES 152576

__global__ void __launch_bounds__(512, 1)
mlp_mma_kernel(const float* __restrict__ b_up, const float* __restrict__ bs,
               const float* __restrict__ W_out, float* __restrict__ out)
{
    extern __shared__ char smem[];
    const uint32_t sb = smem_u32(smem);
    const int t   = threadIdx.x;
    const int wid = t >> 5;
    const int lid = t & 31;
    const int wm  = wid & 3;       // m16 block
    const int wn  = wid >> 2;      // n64 block
    const int node0 = blockIdx.x * 64;

    // ---- initial A: g_v rows -> bf16 hi/lo split into SMEM ----
    {
        const int m    = t >> 3;          // 0..63
        const int kc0  = (t & 7) * 16;    // 16 floats per thread
        const int node = node0 + m;
        float x[16];
        if (node < NUM_NODES) {
            const float4* src =
                reinterpret_cast<const float4*>(g_v + (size_t)node * HIDDEN + kc0);
            #pragma unroll
            for (int i = 0; i < 4; ++i) {
                const float4 v4 = src[i];
                x[4*i] = v4.x; x[4*i+1] = v4.y; x[4*i+2] = v4.z; x[4*i+3] = v4.w;
            }
        } else {
            #pragma unroll
            for (int i = 0; i < 16; ++i) x[i] = 0.f;
        }
        uint32_t hi[8], lo[8];
        #pragma unroll
        for (int j = 0; j < 8; ++j) {
            float h0, l0, h1, l1;
            bsplit(x[2*j], h0, l0);
            bsplit(x[2*j+1], h1, l1);
            hi[j] = packbf2(h0, h1);
            lo[j] = packbf2(l0, l1);
        }
        char* dh = smem + SM_A_HI + m * 528 + kc0 * 2;
        char* dl = smem + SM_A_LO + m * 528 + kc0 * 2;
        #pragma unroll
        for (int u = 0; u < 2; ++u) {
            *reinterpret_cast<uint4*>(dh + u * 16) =
                make_uint4(hi[4*u], hi[4*u+1], hi[4*u+2], hi[4*u+3]);
            *reinterpret_cast<uint4*>(dl + u * 16) =
                make_uint4(lo[4*u], lo[4*u+1], lo[4*u+2], lo[4*u+3]);
        }
    }

    float acc[8][4];

    for (int layer = 0; layer < 4; ++layer) {
        const int K    = (layer == 0) ? HIDDEN : OUT_EMB;
        const int npan = K / 32;
        const int Loff = (layer == 0) ? 0 : 256 * 128 + (layer - 1) * 256 * 256;

        // ---- per-layer constants + stage panel 0 ----
        {
            if (t < 256) {
                reinterpret_cast<float*>(smem + SM_BIAS)[t] =
                    (layer == 0) ? b_up[t] : bs[(layer - 1) * OUT_EMB + t];
                if (layer == 3)
                    reinterpret_cast<float*>(smem + SM_WOUT)[t] = W_out[t];
            }
            const int n = t >> 1;            // 2 threads per row
            const int c = t & 1;             // half-row (16 bf16)
            char* dH = smem + SM_B + n * BROW + c * 32;
            char* dL = dH + BMAT;
            const int src = Loff + n * K + c * 16;
            *reinterpret_cast<uint4*>(dH)      = *reinterpret_cast<const uint4*>(g_wh + src);
            *reinterpret_cast<uint4*>(dH + 16) = *reinterpret_cast<const uint4*>(g_wh + src + 8);
            *reinterpret_cast<uint4*>(dL)      = *reinterpret_cast<const uint4*>(g_wl + src);
            *reinterpret_cast<uint4*>(dL + 16) = *reinterpret_cast<const uint4*>(g_wl + src + 8);
        }
        __syncthreads();

        #pragma unroll
        for (int na = 0; na < 8; ++na)
            #pragma unroll
            for (int i = 0; i < 4; ++i) acc[na][i] = 0.f;

        for (int p = 0; p < npan; ++p) {
            const bool hasNext = (p + 1 < npan);
            uint4 pfH[2], pfL[2];
            if (hasNext) {
                const int n = t >> 1;
                const int c = t & 1;
                const int src0 = Loff + n * K + (p + 1) * 32 + c * 16;
                pfH[0] = *reinterpret_cast<const uint4*>(g_wh + src0);
                pfH[1] = *reinterpret_cast<const uint4*>(g_wh + src0 + 8);
                pfL[0] = *reinterpret_cast<const uint4*>(g_wl + src0);
                pfL[1] = *reinterpret_cast<const uint4*>(g_wl + src0 + 8);
            }

            // ---- compute panel p (k = p*32 .. +31) ----
            const uint32_t bsH = sb + SM_B + (uint32_t)(p & 1) * BSLOT;
            #pragma unroll
            for (int ks = 0; ks < 2; ++ks) {
                const int kk = ks * 16;
                uint32_t Ah[4], Al[4];
                {
                    const int row = wm * 16 + (lid & 7) + ((lid >> 3) & 1) * 8;
                    const int kc  = p * 32 + kk + (lid >> 4) * 8;
                    const uint32_t ad = sb + SM_A_HI + row * 528 + kc * 2;
                    ldsm4(Ah, ad);
                    ldsm4(Al, ad + 33792);
                }
                uint32_t Bh[8][2], Bl[8][2];
                #pragma unroll
                for (int bp = 0; bp < 4; ++bp) {
                    const int n  = wn * 64 + bp * 16 + (lid & 7) + (lid >> 4) * 8;
                    const int kb = kk + ((lid >> 3) & 1) * 8;
                    const uint32_t ad = bsH + n * BROW + kb * 2;
                    uint32_t r[4];
                    ldsm4(r, ad);
                    Bh[2*bp][0] = r[0]; Bh[2*bp][1] = r[1];
                    Bh[2*bp+1][0] = r[2]; Bh[2*bp+1][1] = r[3];
                    ldsm4(r, ad + BMAT);
                    Bl[2*bp][0] = r[0]; Bl[2*bp][1] = r[1];
                    Bl[2*bp+1][0] = r[2]; Bl[2*bp+1][1] = r[3];
                }
                #pragma unroll
                for (int na = 0; na < 8; ++na) {
                    mma16816(acc[na], Ah, Bh[na]);
                    mma16816(acc[na], Ah, Bl[na]);
                    mma16816(acc[na], Al, Bh[na]);
                }
            }

            if (hasNext) {
                const int n = t >> 1;
                const int c = t & 1;
                char* dH = smem + SM_B + ((p + 1) & 1) * BSLOT + n * BROW + c * 32;
                char* dL = dH + BMAT;
                *reinterpret_cast<uint4*>(dH)      = pfH[0];
                *reinterpret_cast<uint4*>(dH + 16) = pfH[1];
                *reinterpret_cast<uint4*>(dL)      = pfL[0];
                *reinterpret_cast<uint4*>(dL + 16) = pfL[1];
            }
            __syncthreads();
        }

        // ---- epilogue ----
        const float* bias_s = reinterpret_cast<const float*>(smem + SM_BIAS);
        if (layer < 3) {
            #pragma unroll
            for (int na = 0; na < 8; ++na) {
                const int col = wn * 64 + na * 8 + (lid & 3) * 2;
                const int r0  = wm * 16 + (lid >> 2);
                const float bv0 = bias_s[col], bv1 = bias_s[col + 1];
                float x0 = acc[na][0] + bv0;
                float x1 = acc[na][1] + bv1;
                float x2 = acc[na][2] + bv0;
                float x3 = acc[na][3] + bv1;
                if (layer > 0) { x0 = silu(x0); x1 = silu(x1); x2 = silu(x2); x3 = silu(x3); }
                float h0,l0,h1,l1,h2,l2,h3,l3;
                bsplit(x0,h0,l0); bsplit(x1,h1,l1);
                bsplit(x2,h2,l2); bsplit(x3,h3,l3);
                *reinterpret_cast<uint32_t*>(smem + SM_A_HI + r0*528 + col*2) = packbf2(h0,h1);
                *reinterpret_cast<uint32_t*>(smem + SM_A_LO + r0*528 + col*2) = packbf2(l0,l1);
                *reinterpret_cast<uint32_t*>(smem + SM_A_HI + (r0+8)*528 + col*2) = packbf2(h2,h3);
                *reinterpret_cast<uint32_t*>(smem + SM_A_LO + (r0+8)*528 + col*2) = packbf2(l2,l3);
            }
            __syncthreads();
        } else {
            const float* wo = reinterpret_cast<const float*>(smem + SM_WOUT);
            float* part = reinterpret_cast<float*>(smem + SM_PART);
            float p0 = 0.f, p1 = 0.f;
            #pragma unroll
            for (int na = 0; na < 8; ++na) {
                const int col = wn * 64 + na * 8 + (lid & 3) * 2;
                const float bv0 = bias_s[col], bv1 = bias_s[col + 1];
                const float w0 = wo[col], w1 = wo[col + 1];
                p0 = fmaf(silu(acc[na][0] + bv0), w0, p0);
                p0 = fmaf(silu(acc[na][1] + bv1), w1, p0);
                p1 = fmaf(silu(acc[na][2] + bv0), w0, p1);
                p1 = fmaf(silu(acc[na][3] + bv1), w1, p1);
            }
            p0 += __shfl_xor_sync(0xffffffffu, p0, 1);
            p0 += __shfl_xor_sync(0xffffffffu, p0, 2);
            p1 += __shfl_xor_sync(0xffffffffu, p1, 1);
            p1 += __shfl_xor_sync(0xffffffffu, p1, 2);
            if ((lid & 3) == 0) {
                const int r0 = wm * 16 + (lid >> 2);
                part[r0 * 4 + wn]       = p0;
                part[(r0 + 8) * 4 + wn] = p1;
            }
            __syncthreads();
            if (t < 64) {
                const int node = node0 + t;
                if (node < NUM_NODES)
                    out[node] = part[4*t] + part[4*t+1] + part[4*t+2] + part[4*t+3];
            }
        }
    }
}

// ---------------------------------------------------------------------------
extern "C" void kernel_launch(void* const* d_in, const int* in_sizes, int n_in,
                              void* d_out, int out_size)
{
    const float* e2    = (const float*)d_in[0];
    const void*  idx   = d_in[1];
    const float* W_up  = (const float*)d_in[2];
    const float* b_up  = (const float*)d_in[3];
    const float* Ws    = (const float*)d_in[4];
    const float* bs    = (const float*)d_in[5];
    const float* W_out = (const float*)d_in[6];
    float* out = (float*)d_out;

    cudaFuncSetAttribute(mlp_mma_kernel,
                         cudaFuncAttributeMaxDynamicSharedMemorySize, SMEM_BYTES);

    detect_idx_kernel<<<1, 1>>>((const int*)idx);
    presplit_kernel<<<(WTOT + 255) / 256, 256>>>(W_up, Ws);

    const int n4 = NUM_NODES * HIDDEN / 4;
    zero_v_kernel<<<(n4 + 255) / 256, 256>>>();

    const long long scatter_threads = (long long)NUM_EDGES * 32;
    scatter_kernel<<<(int)((scatter_threads + 255) / 256), 256>>>(
        (const float4*)e2, idx);

    const int mlp_blocks = (NUM_NODES + 63) / 64;   // 782
    mlp_mma_kernel<<<mlp_blocks, 512, SMEM_BYTES>>>(b_up, bs, W_out, out);
}

// round 13
// speedup vs baseline: 2.0013x; 1.0858x over previous
#include <cuda_runtime.h>
#include <cuda_bf16.h>
#include <cstdint>

#define HIDDEN     128
#define OUT_EMB    256
#define NUM_LAYERS 3
#define NUM_EDGES  1000000
#define NUM_NODES  50000

// ---------------- scratch ----------------------------------------------------
__device__ float g_v[(size_t)NUM_NODES * HIDDEN];
__device__ int   g_idx_is64;
// pre-split weights: layer0 [256][128], layers1-3 [256][256]; hi + lo bf16
#define WTOT (256*128 + 3*256*256)   // 229376
__device__ __align__(16) __nv_bfloat16 g_wh[WTOT];
__device__ __align__(16) __nv_bfloat16 g_wl[WTOT];

// ---------------- small helpers ---------------------------------------------
__device__ __forceinline__ uint32_t smem_u32(const void* p) {
    uint32_t a;
    asm("{ .reg .u64 t; cvta.to.shared.u64 t, %1; cvt.u32.u64 %0, t; }"
        : "=r"(a) : "l"(p));
    return a;
}
__device__ __forceinline__ void bsplit(float x, float& h, float& l) {
    __nv_bfloat16 b = __float2bfloat16(x);
    h = __bfloat162float(b);
    l = x - h;
}
__device__ __forceinline__ uint32_t packbf2(float lo, float hi) {
    __nv_bfloat162 v = __halves2bfloat162(__float2bfloat16(lo), __float2bfloat16(hi));
    return *reinterpret_cast<uint32_t*>(&v);
}
__device__ __forceinline__ void ldsm4(uint32_t* r, uint32_t addr) {
    asm volatile("ldmatrix.sync.aligned.m8n8.x4.shared.b16 {%0,%1,%2,%3}, [%4];"
                 : "=r"(r[0]), "=r"(r[1]), "=r"(r[2]), "=r"(r[3]) : "r"(addr));
}
__device__ __forceinline__ void mma16816(float* d, const uint32_t* a, const uint32_t* b) {
    asm volatile("mma.sync.aligned.m16n8k16.row.col.f32.bf16.bf16.f32 "
                 "{%0,%1,%2,%3}, {%4,%5,%6,%7}, {%8,%9}, {%0,%1,%2,%3};"
                 : "+f"(d[0]), "+f"(d[1]), "+f"(d[2]), "+f"(d[3])
                 : "r"(a[0]), "r"(a[1]), "r"(a[2]), "r"(a[3]),
                   "r"(b[0]), "r"(b[1]));
}
__device__ __forceinline__ float silu(float x) { return x / (1.f + __expf(-x)); }

// ---------------- front kernels ----------------------------------------------
__global__ void detect_idx_kernel(const int* __restrict__ idx) {
    if (blockIdx.x == 0 && threadIdx.x == 0) {
        int z = 0;
        #pragma unroll
        for (int j = 1; j < 64; j += 2) z |= idx[j];
        g_idx_is64 = (z == 0) ? 1 : 0;
    }
}

__global__ void zero_v_kernel() {
    const int i  = blockIdx.x * blockDim.x + threadIdx.x;
    const int n4 = NUM_NODES * HIDDEN / 4;
    if (i < n4) reinterpret_cast<float4*>(g_v)[i] = make_float4(0.f, 0.f, 0.f, 0.f);
}

__global__ void presplit_kernel(const float* __restrict__ W_up,
                                const float* __restrict__ Ws) {
    const int i = blockIdx.x * blockDim.x + threadIdx.x;
    if (i >= WTOT) return;
    const float v = (i < 256 * 128) ? W_up[i] : Ws[i - 256 * 128];
    float h, l;
    bsplit(v, h, l);
    g_wh[i] = __float2bfloat16(h);
    g_wl[i] = __float2bfloat16(l);
}

__global__ void scatter_kernel(const float4* __restrict__ e2,
                               const void*   __restrict__ idx_raw) {
    const long long g = (long long)blockIdx.x * blockDim.x + threadIdx.x;
    if (g >= (long long)NUM_EDGES * 32) return;
    const int edge = (int)(g >> 5);
    const int lane = (int)(g & 31);
    int node;
    if (g_idx_is64) node = (int)reinterpret_cast<const long long*>(idx_raw)[edge];
    else            node = reinterpret_cast<const int*>(idx_raw)[edge];
    const float4 val = e2[(long long)edge * 32 + lane];
    float* dst = g_v + (size_t)node * HIDDEN + (size_t)lane * 4;
    asm volatile("red.global.add.v4.f32 [%0], {%1, %2, %3, %4};"
                 :: "l"(dst), "f"(val.x), "f"(val.y), "f"(val.z), "f"(val.w)
                 : "memory");
}

// ---------------- tensor-core MLP (1024 threads, 32 warps) --------------------
// Warp w: wm = w&3 -> rows wm*16..+15 ; wn = w>>2 (0..7) -> cols wn*32..+31.
// Per warp per k16-step: 2 A-ldsm (hi/lo) + 4 B-ldsm, 12 HMMA (4 tiles x 3).
// SMEM: A rows 528 B; B rows 80 B (conflict-free phases), double-buffered.
#define SM_A_HI  0
#define SM_A_LO  33792                      // 64*528
#define BROW     80
#define BMAT     20480                      // 256*80
#define BSLOT    40960                      // hi + lo
#define SM_B     67584
#define SM_BIAS  149504
#define SM_WOUT  150528
#define SM_PART  151552                     // 64 rows x 8 n-blocks x f32 = 2 KB
#define SMEM_BYTES 153600

__global__ void __launch_bounds__(1024, 1)
mlp_mma_kernel(const float* __restrict__ b_up, const float* __restrict__ bs,
               const float* __restrict__ W_out, float* __restrict__ out)
{
    extern __shared__ char smem[];
    const uint32_t sb = smem_u32(smem);
    const int t   = threadIdx.x;
    const int wid = t >> 5;
    const int lid = t & 31;
    const int wm  = wid & 3;       // m16 block
    const int wn  = wid >> 2;      // n32 block (0..7)
    const int node0 = blockIdx.x * 64;

    // ---- initial A: g_v rows -> bf16 hi/lo split into SMEM ----
    {
        const int m    = t >> 4;          // 0..63
        const int kc0  = (t & 15) * 8;    // 8 floats per thread
        const int node = node0 + m;
        float x[8];
        if (node < NUM_NODES) {
            const float4* src =
                reinterpret_cast<const float4*>(g_v + (size_t)node * HIDDEN + kc0);
            #pragma unroll
            for (int i = 0; i < 2; ++i) {
                const float4 v4 = src[i];
                x[4*i] = v4.x; x[4*i+1] = v4.y; x[4*i+2] = v4.z; x[4*i+3] = v4.w;
            }
        } else {
            #pragma unroll
            for (int i = 0; i < 8; ++i) x[i] = 0.f;
        }
        uint32_t hi[4], lo[4];
        #pragma unroll
        for (int j = 0; j < 4; ++j) {
            float h0, l0, h1, l1;
            bsplit(x[2*j], h0, l0);
            bsplit(x[2*j+1], h1, l1);
            hi[j] = packbf2(h0, h1);
            lo[j] = packbf2(l0, l1);
        }
        *reinterpret_cast<uint4*>(smem + SM_A_HI + m * 528 + kc0 * 2) =
            make_uint4(hi[0], hi[1], hi[2], hi[3]);
        *reinterpret_cast<uint4*>(smem + SM_A_LO + m * 528 + kc0 * 2) =
            make_uint4(lo[0], lo[1], lo[2], lo[3]);
    }

    float acc[4][4];

    for (int layer = 0; layer < 4; ++layer) {
        const int K    = (layer == 0) ? HIDDEN : OUT_EMB;
        const int npan = K / 32;
        const int Loff = (layer == 0) ? 0 : 256 * 128 + (layer - 1) * 256 * 256;

        // ---- per-layer constants + stage panel 0 ----
        {
            if (t < 256) {
                reinterpret_cast<float*>(smem + SM_BIAS)[t] =
                    (layer == 0) ? b_up[t] : bs[(layer - 1) * OUT_EMB + t];
                if (layer == 3)
                    reinterpret_cast<float*>(smem + SM_WOUT)[t] = W_out[t];
            }
            const int n = t >> 2;            // 4 threads per row
            const int c = t & 3;             // 16B chunk (8 bf16)
            char* dH = smem + SM_B + n * BROW + c * 16;
            char* dL = dH + BMAT;
            const int src = Loff + n * K + c * 8;
            *reinterpret_cast<uint4*>(dH) = *reinterpret_cast<const uint4*>(g_wh + src);
            *reinterpret_cast<uint4*>(dL) = *reinterpret_cast<const uint4*>(g_wl + src);
        }
        __syncthreads();

        #pragma unroll
        for (int na = 0; na < 4; ++na)
            #pragma unroll
            for (int i = 0; i < 4; ++i) acc[na][i] = 0.f;

        for (int p = 0; p < npan; ++p) {
            const bool hasNext = (p + 1 < npan);
            uint4 pfH, pfL;
            if (hasNext) {
                const int n = t >> 2;
                const int c = t & 3;
                const int src0 = Loff + n * K + (p + 1) * 32 + c * 8;
                pfH = *reinterpret_cast<const uint4*>(g_wh + src0);
                pfL = *reinterpret_cast<const uint4*>(g_wl + src0);
            }

            // ---- compute panel p (k = p*32 .. +31) ----
            const uint32_t bsH = sb + SM_B + (uint32_t)(p & 1) * BSLOT;
            #pragma unroll
            for (int ks = 0; ks < 2; ++ks) {
                const int kk = ks * 16;
                uint32_t Ah[4], Al[4];
                {
                    const int row = wm * 16 + (lid & 7) + ((lid >> 3) & 1) * 8;
                    const int kc  = p * 32 + kk + (lid >> 4) * 8;
                    const uint32_t ad = sb + SM_A_HI + row * 528 + kc * 2;
                    ldsm4(Ah, ad);
                    ldsm4(Al, ad + 33792);
                }
                uint32_t Bh[4][2], Bl[4][2];
                #pragma unroll
                for (int bp = 0; bp < 2; ++bp) {
                    const int n  = wn * 32 + bp * 16 + (lid & 7) + (lid >> 4) * 8;
                    const int kb = kk + ((lid >> 3) & 1) * 8;
                    const uint32_t ad = bsH + n * BROW + kb * 2;
                    uint32_t r[4];
                    ldsm4(r, ad);
                    Bh[2*bp][0] = r[0]; Bh[2*bp][1] = r[1];
                    Bh[2*bp+1][0] = r[2]; Bh[2*bp+1][1] = r[3];
                    ldsm4(r, ad + BMAT);
                    Bl[2*bp][0] = r[0]; Bl[2*bp][1] = r[1];
                    Bl[2*bp+1][0] = r[2]; Bl[2*bp+1][1] = r[3];
                }
                #pragma unroll
                for (int na = 0; na < 4; ++na) {
                    mma16816(acc[na], Ah, Bh[na]);
                    mma16816(acc[na], Ah, Bl[na]);
                    mma16816(acc[na], Al, Bh[na]);
                }
            }

            if (hasNext) {
                const int n = t >> 2;
                const int c = t & 3;
                char* dH = smem + SM_B + ((p + 1) & 1) * BSLOT + n * BROW + c * 16;
                char* dL = dH + BMAT;
                *reinterpret_cast<uint4*>(dH) = pfH;
                *reinterpret_cast<uint4*>(dL) = pfL;
            }
            __syncthreads();
        }

        // ---- epilogue ----
        const float* bias_s = reinterpret_cast<const float*>(smem + SM_BIAS);
        if (layer < 3) {
            #pragma unroll
            for (int na = 0; na < 4; ++na) {
                const int col = wn * 32 + na * 8 + (lid & 3) * 2;
                const int r0  = wm * 16 + (lid >> 2);
                const float bv0 = bias_s[col], bv1 = bias_s[col + 1];
                float x0 = acc[na][0] + bv0;
                float x1 = acc[na][1] + bv1;
                float x2 = acc[na][2] + bv0;
                float x3 = acc[na][3] + bv1;
                if (layer > 0) { x0 = silu(x0); x1 = silu(x1); x2 = silu(x2); x3 = silu(x3); }
                float h0,l0,h1,l1,h2,l2,h3,l3;
                bsplit(x0,h0,l0); bsplit(x1,h1,l1);
                bsplit(x2,h2,l2); bsplit(x3,h3,l3);
                *reinterpret_cast<uint32_t*>(smem + SM_A_HI + r0*528 + col*2) = packbf2(h0,h1);
                *reinterpret_cast<uint32_t*>(smem + SM_A_LO + r0*528 + col*2) = packbf2(l0,l1);
                *reinterpret_cast<uint32_t*>(smem + SM_A_HI + (r0+8)*528 + col*2) = packbf2(h2,h3);
                *reinterpret_cast<uint32_t*>(smem + SM_A_LO + (r0+8)*528 + col*2) = packbf2(l2,l3);
            }
            __syncthreads();
        } else {
            const float* wo = reinterpret_cast<const float*>(smem + SM_WOUT);
            float* part = reinterpret_cast<float*>(smem + SM_PART);
            float p0 = 0.f, p1 = 0.f;
            #pragma unroll
            for (int na = 0; na < 4; ++na) {
                const int col = wn * 32 + na * 8 + (lid & 3) * 2;
                const float bv0 = bias_s[col], bv1 = bias_s[col + 1];
                const float w0 = wo[col], w1 = wo[col + 1];
                p0 = fmaf(silu(acc[na][0] + bv0), w0, p0);
                p0 = fmaf(silu(acc[na][1] + bv1), w1, p0);
                p1 = fmaf(silu(acc[na][2] + bv0), w0, p1);
                p1 = fmaf(silu(acc[na][3] + bv1), w1, p1);
            }
            p0 += __shfl_xor_sync(0xffffffffu, p0, 1);
            p0 += __shfl_xor_sync(0xffffffffu, p0, 2);
            p1 += __shfl_xor_sync(0xffffffffu, p1, 1);
            p1 += __shfl_xor_sync(0xffffffffu, p1, 2);
            if ((lid & 3) == 0) {
                const int r0 = wm * 16 + (lid >> 2);
                part[r0 * 8 + wn]       = p0;
                part[(r0 + 8) * 8 + wn] = p1;
            }
            __syncthreads();
            if (t < 64) {
                const int node = node0 + t;
                if (node < NUM_NODES) {
                    float s = 0.f;
                    #pragma unroll
                    for (int q = 0; q < 8; ++q) s += part[8*t + q];
                    out[node] = s;
                }
            }
        }
    }
}

// ---------------------------------------------------------------------------
extern "C" void kernel_launch(void* const* d_in, const int* in_sizes, int n_in,
                              void* d_out, int out_size)
{
    const float* e2    = (const float*)d_in[0];
    const void*  idx   = d_in[1];
    const float* W_up  = (const float*)d_in[2];
    const float* b_up  = (const float*)d_in[3];
    const float* Ws    = (const float*)d_in[4];
    const float* bs    = (const float*)d_in[5];
    const float* W_out = (const float*)d_in[6];
    float* out = (float*)d_out;

    cudaFuncSetAttribute(mlp_mma_kernel,
                         cudaFuncAttributeMaxDynamicSharedMemorySize, SMEM_BYTES);

    detect_idx_kernel<<<1, 1>>>((const int*)idx);
    presplit_kernel<<<(WTOT + 255) / 256, 256>>>(W_up, Ws);

    const int n4 = NUM_NODES * HIDDEN / 4;
    zero_v_kernel<<<(n4 + 255) / 256, 256>>>();

    const long long scatter_threads = (long long)NUM_EDGES * 32;
    scatter_kernel<<<(int)((scatter_threads + 255) / 256), 256>>>(
        (const float4*)e2, idx);

    const int mlp_blocks = (NUM_NODES + 63) / 64;   // 782
    mlp_mma_kernel<<<mlp_blocks, 1024, SMEM_BYTES>>>(b_up, bs, W_out, out);
}

// round 14
// speedup vs baseline: 2.1430x; 1.0708x over previous
#include <cuda_runtime.h>
#include <cuda_bf16.h>
#include <cstdint>

#define HIDDEN     128
#define OUT_EMB    256
#define NUM_LAYERS 3
#define NUM_EDGES  1000000
#define NUM_NODES  50000

// ---------------- scratch ----------------------------------------------------
__device__ float g_v[(size_t)NUM_NODES * HIDDEN];
__device__ int   g_idx_is64;
// pre-split weights: layer0 [256][128], layers1-3 [256][256]; hi + lo bf16
#define WTOT (256*128 + 3*256*256)   // 229376
__device__ __align__(16) __nv_bfloat16 g_wh[WTOT];
__device__ __align__(16) __nv_bfloat16 g_wl[WTOT];

// ---------------- small helpers ---------------------------------------------
__device__ __forceinline__ uint32_t smem_u32(const void* p) {
    uint32_t a;
    asm("{ .reg .u64 t; cvta.to.shared.u64 t, %1; cvt.u32.u64 %0, t; }"
        : "=r"(a) : "l"(p));
    return a;
}
__device__ __forceinline__ void bsplit(float x, float& h, float& l) {
    __nv_bfloat16 b = __float2bfloat16(x);
    h = __bfloat162float(b);
    l = x - h;
}
__device__ __forceinline__ uint32_t packbf2(float lo, float hi) {
    __nv_bfloat162 v = __halves2bfloat162(__float2bfloat16(lo), __float2bfloat16(hi));
    return *reinterpret_cast<uint32_t*>(&v);
}
__device__ __forceinline__ void ldsm4(uint32_t* r, uint32_t addr) {
    asm volatile("ldmatrix.sync.aligned.m8n8.x4.shared.b16 {%0,%1,%2,%3}, [%4];"
                 : "=r"(r[0]), "=r"(r[1]), "=r"(r[2]), "=r"(r[3]) : "r"(addr));
}
__device__ __forceinline__ void mma16816(float* d, const uint32_t* a, const uint32_t* b) {
    asm volatile("mma.sync.aligned.m16n8k16.row.col.f32.bf16.bf16.f32 "
                 "{%0,%1,%2,%3}, {%4,%5,%6,%7}, {%8,%9}, {%0,%1,%2,%3};"
                 : "+f"(d[0]), "+f"(d[1]), "+f"(d[2]), "+f"(d[3])
                 : "r"(a[0]), "r"(a[1]), "r"(a[2]), "r"(a[3]),
                   "r"(b[0]), "r"(b[1]));
}
__device__ __forceinline__ float silu(float x) { return x / (1.f + __expf(-x)); }

// ---------------- front kernels ----------------------------------------------
__global__ void detect_idx_kernel(const int* __restrict__ idx) {
    if (blockIdx.x == 0 && threadIdx.x == 0) {
        int z = 0;
        #pragma unroll
        for (int j = 1; j < 64; j += 2) z |= idx[j];
        g_idx_is64 = (z == 0) ? 1 : 0;
    }
}

__global__ void zero_v_kernel() {
    const int i  = blockIdx.x * blockDim.x + threadIdx.x;
    const int n4 = NUM_NODES * HIDDEN / 4;
    if (i < n4) reinterpret_cast<float4*>(g_v)[i] = make_float4(0.f, 0.f, 0.f, 0.f);
}

__global__ void presplit_kernel(const float* __restrict__ W_up,
                                const float* __restrict__ Ws) {
    const int i = blockIdx.x * blockDim.x + threadIdx.x;
    if (i >= WTOT) return;
    const float v = (i < 256 * 128) ? W_up[i] : Ws[i - 256 * 128];
    float h, l;
    bsplit(v, h, l);
    g_wh[i] = __float2bfloat16(h);
    g_wl[i] = __float2bfloat16(l);
}

__global__ void scatter_kernel(const float4* __restrict__ e2,
                               const void*   __restrict__ idx_raw) {
    const long long g = (long long)blockIdx.x * blockDim.x + threadIdx.x;
    if (g >= (long long)NUM_EDGES * 32) return;
    const int edge = (int)(g >> 5);
    const int lane = (int)(g & 31);
    int node;
    if (g_idx_is64) node = (int)reinterpret_cast<const long long*>(idx_raw)[edge];
    else            node = reinterpret_cast<const int*>(idx_raw)[edge];
    const float4 val = e2[(long long)edge * 32 + lane];
    float* dst = g_v + (size_t)node * HIDDEN + (size_t)lane * 4;
    asm volatile("red.global.add.v4.f32 [%0], {%1, %2, %3, %4};"
                 :: "l"(dst), "f"(val.x), "f"(val.y), "f"(val.z), "f"(val.w)
                 : "memory");
}

// ---------------- tensor-core MLP (512 threads, 16 warps, M=128) -------------
// Warp w: wm = w&3 -> rows wm*32..+31 ; wn = w>>2 -> cols wn*64..+63.
// Warp tile m32n64: per k16-step 4 A-ldsm + 8 B-ldsm feed 48 HMMA (128 B/mma,
// 2x better SMEM amortization than m16n32).
// SMEM: A rows 528 B; B rows 80 B (conflict-free phases), double-buffered.
#define SM_A_HI  0
#define SM_A_LO  67584                      // 128*528
#define BROW     80
#define BMAT     20480                      // 256*80
#define BSLOT    40960                      // hi + lo
#define SM_B     135168
#define SM_BIAS  217088                     // 135168 + 2*40960
#define SM_WOUT  218112
#define SM_PART  219136                     // 128 rows x 4 n-blocks x f32 = 2 KB
#define SMEM_BYTES 221184

__global__ void __launch_bounds__(512, 1)
mlp_mma_kernel(const float* __restrict__ b_up, const float* __restrict__ bs,
               const float* __restrict__ W_out, float* __restrict__ out)
{
    extern __shared__ char smem[];
    const uint32_t sb = smem_u32(smem);
    const int t   = threadIdx.x;
    const int wid = t >> 5;
    const int lid = t & 31;
    const int wm  = wid & 3;       // m32 block (0..3)
    const int wn  = wid >> 2;      // n64 block (0..3)
    const int node0 = blockIdx.x * 128;

    // ---- initial A: g_v rows -> bf16 hi/lo split into SMEM ----
    {
        const int m    = t >> 2;          // 0..127
        const int kc0  = (t & 3) * 32;    // 32 floats per thread
        const int node = node0 + m;
        float x[32];
        if (node < NUM_NODES) {
            const float4* src =
                reinterpret_cast<const float4*>(g_v + (size_t)node * HIDDEN + kc0);
            #pragma unroll
            for (int i = 0; i < 8; ++i) {
                const float4 v4 = src[i];
                x[4*i] = v4.x; x[4*i+1] = v4.y; x[4*i+2] = v4.z; x[4*i+3] = v4.w;
            }
        } else {
            #pragma unroll
            for (int i = 0; i < 32; ++i) x[i] = 0.f;
        }
        uint32_t hi[16], lo[16];
        #pragma unroll
        for (int j = 0; j < 16; ++j) {
            float h0, l0, h1, l1;
            bsplit(x[2*j], h0, l0);
            bsplit(x[2*j+1], h1, l1);
            hi[j] = packbf2(h0, h1);
            lo[j] = packbf2(l0, l1);
        }
        char* dh = smem + SM_A_HI + m * 528 + kc0 * 2;
        char* dl = smem + SM_A_LO + m * 528 + kc0 * 2;
        #pragma unroll
        for (int u = 0; u < 4; ++u) {
            *reinterpret_cast<uint4*>(dh + u * 16) =
                make_uint4(hi[4*u], hi[4*u+1], hi[4*u+2], hi[4*u+3]);
            *reinterpret_cast<uint4*>(dl + u * 16) =
                make_uint4(lo[4*u], lo[4*u+1], lo[4*u+2], lo[4*u+3]);
        }
    }

    float acc[2][8][4];

    for (int layer = 0; layer < 4; ++layer) {
        const int K    = (layer == 0) ? HIDDEN : OUT_EMB;
        const int npan = K / 32;
        const int Loff = (layer == 0) ? 0 : 256 * 128 + (layer - 1) * 256 * 256;

        // ---- per-layer constants + stage panel 0 ----
        {
            if (t < 256) {
                reinterpret_cast<float*>(smem + SM_BIAS)[t] =
                    (layer == 0) ? b_up[t] : bs[(layer - 1) * OUT_EMB + t];
                if (layer == 3)
                    reinterpret_cast<float*>(smem + SM_WOUT)[t] = W_out[t];
            }
            const int n = t >> 1;            // 2 threads per row
            const int c = t & 1;             // half-row (16 bf16)
            char* dH = smem + SM_B + n * BROW + c * 32;
            char* dL = dH + BMAT;
            const int src = Loff + n * K + c * 16;
            *reinterpret_cast<uint4*>(dH)      = *reinterpret_cast<const uint4*>(g_wh + src);
            *reinterpret_cast<uint4*>(dH + 16) = *reinterpret_cast<const uint4*>(g_wh + src + 8);
            *reinterpret_cast<uint4*>(dL)      = *reinterpret_cast<const uint4*>(g_wl + src);
            *reinterpret_cast<uint4*>(dL + 16) = *reinterpret_cast<const uint4*>(g_wl + src + 8);
        }
        __syncthreads();

        #pragma unroll
        for (int ma = 0; ma < 2; ++ma)
            #pragma unroll
            for (int na = 0; na < 8; ++na)
                #pragma unroll
                for (int i = 0; i < 4; ++i) acc[ma][na][i] = 0.f;

        for (int p = 0; p < npan; ++p) {
            const bool hasNext = (p + 1 < npan);
            uint4 pfH[2], pfL[2];
            if (hasNext) {
                const int n = t >> 1;
                const int c = t & 1;
                const int src0 = Loff + n * K + (p + 1) * 32 + c * 16;
                pfH[0] = *reinterpret_cast<const uint4*>(g_wh + src0);
                pfH[1] = *reinterpret_cast<const uint4*>(g_wh + src0 + 8);
                pfL[0] = *reinterpret_cast<const uint4*>(g_wl + src0);
                pfL[1] = *reinterpret_cast<const uint4*>(g_wl + src0 + 8);
            }

            // ---- compute panel p (k = p*32 .. +31) ----
            const uint32_t bsH = sb + SM_B + (uint32_t)(p & 1) * BSLOT;
            #pragma unroll
            for (int ks = 0; ks < 2; ++ks) {
                const int kk = ks * 16;
                uint32_t Ah[2][4], Al[2][4];
                #pragma unroll
                for (int ma = 0; ma < 2; ++ma) {
                    const int row = wm * 32 + ma * 16 + (lid & 7) + ((lid >> 3) & 1) * 8;
                    const int kc  = p * 32 + kk + (lid >> 4) * 8;
                    const uint32_t ad = sb + SM_A_HI + row * 528 + kc * 2;
                    ldsm4(Ah[ma], ad);
                    ldsm4(Al[ma], ad + SM_A_LO);
                }
                uint32_t Bh[8][2], Bl[8][2];
                #pragma unroll
                for (int bp = 0; bp < 4; ++bp) {
                    const int n  = wn * 64 + bp * 16 + (lid & 7) + (lid >> 4) * 8;
                    const int kb = kk + ((lid >> 3) & 1) * 8;
                    const uint32_t ad = bsH + n * BROW + kb * 2;
                    uint32_t r[4];
                    ldsm4(r, ad);
                    Bh[2*bp][0] = r[0]; Bh[2*bp][1] = r[1];
                    Bh[2*bp+1][0] = r[2]; Bh[2*bp+1][1] = r[3];
                    ldsm4(r, ad + BMAT);
                    Bl[2*bp][0] = r[0]; Bl[2*bp][1] = r[1];
                    Bl[2*bp+1][0] = r[2]; Bl[2*bp+1][1] = r[3];
                }
                #pragma unroll
                for (int ma = 0; ma < 2; ++ma)
                    #pragma unroll
                    for (int na = 0; na < 8; ++na) {
                        mma16816(acc[ma][na], Ah[ma], Bh[na]);
                        mma16816(acc[ma][na], Ah[ma], Bl[na]);
                        mma16816(acc[ma][na], Al[ma], Bh[na]);
                    }
            }

            if (hasNext) {
                const int n = t >> 1;
                const int c = t & 1;
                char* dH = smem + SM_B + ((p + 1) & 1) * BSLOT + n * BROW + c * 32;
                char* dL = dH + BMAT;
                *reinterpret_cast<uint4*>(dH)      = pfH[0];
                *reinterpret_cast<uint4*>(dH + 16) = pfH[1];
                *reinterpret_cast<uint4*>(dL)      = pfL[0];
                *reinterpret_cast<uint4*>(dL + 16) = pfL[1];
            }
            __syncthreads();
        }

        // ---- epilogue ----
        const float* bias_s = reinterpret_cast<const float*>(smem + SM_BIAS);
        if (layer < 3) {
            #pragma unroll
            for (int ma = 0; ma < 2; ++ma)
                #pragma unroll
                for (int na = 0; na < 8; ++na) {
                    const int col = wn * 64 + na * 8 + (lid & 3) * 2;
                    const int r0  = wm * 32 + ma * 16 + (lid >> 2);
                    const float bv0 = bias_s[col], bv1 = bias_s[col + 1];
                    float x0 = acc[ma][na][0] + bv0;
                    float x1 = acc[ma][na][1] + bv1;
                    float x2 = acc[ma][na][2] + bv0;
                    float x3 = acc[ma][na][3] + bv1;
                    if (layer > 0) { x0 = silu(x0); x1 = silu(x1); x2 = silu(x2); x3 = silu(x3); }
                    float h0,l0,h1,l1,h2,l2,h3,l3;
                    bsplit(x0,h0,l0); bsplit(x1,h1,l1);
                    bsplit(x2,h2,l2); bsplit(x3,h3,l3);
                    *reinterpret_cast<uint32_t*>(smem + SM_A_HI + r0*528 + col*2) = packbf2(h0,h1);
                    *reinterpret_cast<uint32_t*>(smem + SM_A_LO + r0*528 + col*2) = packbf2(l0,l1);
                    *reinterpret_cast<uint32_t*>(smem + SM_A_HI + (r0+8)*528 + col*2) = packbf2(h2,h3);
                    *reinterpret_cast<uint32_t*>(smem + SM_A_LO + (r0+8)*528 + col*2) = packbf2(l2,l3);
                }
            __syncthreads();
        } else {
            const float* wo = reinterpret_cast<const float*>(smem + SM_WOUT);
            float* part = reinterpret_cast<float*>(smem + SM_PART);
            #pragma unroll
            for (int ma = 0; ma < 2; ++ma) {
                float p0 = 0.f, p1 = 0.f;
                #pragma unroll
                for (int na = 0; na < 8; ++na) {
                    const int col = wn * 64 + na * 8 + (lid & 3) * 2;
                    const float bv0 = bias_s[col], bv1 = bias_s[col + 1];
                    const float w0 = wo[col], w1 = wo[col + 1];
                    p0 = fmaf(silu(acc[ma][na][0] + bv0), w0, p0);
                    p0 = fmaf(silu(acc[ma][na][1] + bv1), w1, p0);
                    p1 = fmaf(silu(acc[ma][na][2] + bv0), w0, p1);
                    p1 = fmaf(silu(acc[ma][na][3] + bv1), w1, p1);
                }
                p0 += __shfl_xor_sync(0xffffffffu, p0, 1);
                p0 += __shfl_xor_sync(0xffffffffu, p0, 2);
                p1 += __shfl_xor_sync(0xffffffffu, p1, 1);
                p1 += __shfl_xor_sync(0xffffffffu, p1, 2);
                if ((lid & 3) == 0) {
                    const int r0 = wm * 32 + ma * 16 + (lid >> 2);
                    part[r0 * 4 + wn]       = p0;
                    part[(r0 + 8) * 4 + wn] = p1;
                }
            }
            __syncthreads();
            if (t < 128) {
                const int node = node0 + t;
                if (node < NUM_NODES)
                    out[node] = part[4*t] + part[4*t+1] + part[4*t+2] + part[4*t+3];
            }
        }
    }
}

// ---------------------------------------------------------------------------
extern "C" void kernel_launch(void* const* d_in, const int* in_sizes, int n_in,
                              void* d_out, int out_size)
{
    const float* e2    = (const float*)d_in[0];
    const void*  idx   = d_in[1];
    const float* W_up  = (const float*)d_in[2];
    const float* b_up  = (const float*)d_in[3];
    const float* Ws    = (const float*)d_in[4];
    const float* bs    = (const float*)d_in[5];
    const float* W_out = (const float*)d_in[6];
    float* out = (float*)d_out;

    cudaFuncSetAttribute(mlp_mma_kernel,
                         cudaFuncAttributeMaxDynamicSharedMemorySize, SMEM_BYTES);

    detect_idx_kernel<<<1, 1>>>((const int*)idx);
    presplit_kernel<<<(WTOT + 255) / 256, 256>>>(W_up, Ws);

    const int n4 = NUM_NODES * HIDDEN / 4;
    zero_v_kernel<<<(n4 + 255) / 256, 256>>>();

    const long long scatter_threads = (long long)NUM_EDGES * 32;
    scatter_kernel<<<(int)((scatter_threads + 255) / 256), 256>>>(
        (const float4*)e2, idx);

    const int mlp_blocks = (NUM_NODES + 127) / 128;   // 391
    mlp_mma_kernel<<<mlp_blocks, 512, SMEM_BYTES>>>(b_up, bs, W_out, out);
}